// round 10
// baseline (speedup 1.0000x reference)
#include <cuda_runtime.h>
#include <cstdint>

#define N_BOX     8192
#define MAX_KEEP  256
#define MIN_SCORE 0.3f
#define NMS_THR   0.3f
#define NT        1024
#define NBKT      8192
#define NCHUNK    128          // 64-bit words per mask row (8192/64)
#define FULL      0xFFFFFFFFu

// ---------------- global scratch (static __device__, no allocation) ----------------
__device__ unsigned long long g_key[N_BOX];        // sorted keys (~score_bits, idx)
__device__ float4             g_cbox[N_BOX];       // sorted xyxy boxes
__device__ unsigned long long g_mask[N_BOX * NCHUNK];  // 8 MB suppression bitmask
__device__ int                g_nval;

// ================= kernel A: bucket sort (exact stable descending) =================
extern __shared__ unsigned char dynsmem[];

__global__ void __launch_bounds__(NT, 1)
sort_kernel(const float* __restrict__ score, const float* __restrict__ box)
{
    unsigned long long* s_key = (unsigned long long*)dynsmem;          // 64 KB
    unsigned int*       s_cnt = (unsigned int*)(dynsmem + 65536);      // 32 KB
    unsigned int*       s_off = (unsigned int*)(dynsmem + 98304);      // 32 KB
    __shared__ unsigned int s_wsum[32];
    __shared__ int s_nvalid;

    const int tid  = threadIdx.x;
    const int lane = tid & 31;
    const int wid  = tid >> 5;

    for (int i = tid; i < NBKT; i += NT) s_cnt[i] = 0;
    __syncthreads();

    float sc[8]; int bk[8];
    #pragma unroll
    for (int k = 0; k < 8; k++) {
        int i = tid + k * NT;
        float s = score[i];
        sc[k] = s;
        int b = -1;
        if (s >= MIN_SCORE) {
            b = 8191 - min(8191, (int)(s * 8192.0f));   // score desc -> bucket asc (monotone)
            atomicAdd(&s_cnt[b], 1u);
        }
        bk[k] = b;
    }
    __syncthreads();

    // exclusive scan of 8192 counters (1024 threads x 8)
    unsigned int c[8], tsum = 0;
    #pragma unroll
    for (int q = 0; q < 8; q++) { c[q] = s_cnt[tid*8+q]; tsum += c[q]; }
    unsigned int p = tsum;
    #pragma unroll
    for (int d = 1; d < 32; d <<= 1) {
        unsigned int v = __shfl_up_sync(FULL, p, d);
        if (lane >= d) p += v;
    }
    if (lane == 31) s_wsum[wid] = p;
    __syncthreads();
    if (wid == 0) {
        unsigned int w = s_wsum[lane];
        unsigned int q = w;
        #pragma unroll
        for (int d = 1; d < 32; d <<= 1) {
            unsigned int v = __shfl_up_sync(FULL, q, d);
            if (lane >= d) q += v;
        }
        s_wsum[lane] = q - w;
        if (lane == 31) s_nvalid = (int)q;
    }
    __syncthreads();
    unsigned int run = s_wsum[wid] + (p - tsum);
    #pragma unroll
    for (int q = 0; q < 8; q++) { s_off[tid*8+q] = run; run += c[q]; }
    __syncthreads();

    // scatter (afterwards s_off[b] = start of bucket b+1)
    #pragma unroll
    for (int k = 0; k < 8; k++) {
        if (bk[k] >= 0) {
            int i = tid + k * NT;
            unsigned int pos = atomicAdd(&s_off[bk[k]], 1u);
            s_key[pos] = ((unsigned long long)(~__float_as_uint(sc[k])) << 32) | (unsigned int)i;
        }
    }
    __syncthreads();

    // intra-bucket insertion sort on full u64 key (exact total order)
    for (int b = tid; b < NBKT; b += NT) {
        int lo = b ? (int)s_off[b-1] : 0;
        int hi = (int)s_off[b];
        for (int i = lo + 1; i < hi; i++) {
            unsigned long long v = s_key[i];
            int j = i - 1;
            while (j >= lo && s_key[j] > v) { s_key[j+1] = s_key[j]; j--; }
            s_key[j+1] = v;
        }
    }
    __syncthreads();

    const int nval = s_nvalid;
    for (int cc = tid; cc < nval; cc += NT) {
        unsigned long long key = s_key[cc];
        g_key[cc] = key;
        int idx = (int)(key & 0xFFFFFFFFull);
        float4 b4 = *(const float4*)(box + idx * 16);
        float hw = b4.z * 0.5f, hh = b4.w * 0.5f;
        g_cbox[cc] = make_float4(b4.x - hw, b4.y - hh, b4.x + hw, b4.y + hh);
    }
    if (tid == 0) g_nval = nval;
}

// ================= kernel B: suppression bitmask matrix (multi-SM) =================
// grid (32 row-tiles, 16 word-groups); block = 256 threads = 256 rows; each thread
// computes 8 mask words (512 columns) against a shared 512-box tile.
// Division-free threshold test, bit-exact vs reference (guarded multiply-compare with
// exact-division fallback only inside a +-1e-6 relative window around the threshold).
#define WG 8            // words per thread / per group
__global__ void __launch_bounds__(256)
mask_kernel()
{
    const int by   = blockIdx.y;             // word group 0..15 (words by*8 .. by*8+7)
    const int i0   = blockIdx.x * 256;       // row tile base
    const int nval = g_nval;
    if (i0 >= nval) return;
    const int jtile = by * (WG * 64);        // first column of this tile
    if (jtile + WG * 64 - 1 <= i0) return;   // whole tile j <= all rows -> never read
    if (jtile >= ((nval + 63) & ~63)) return;// whole tile beyond last readable word

    __shared__ float4 cb[WG * 64];
    __shared__ float  car[WG * 64];
    const int t = threadIdx.x;
    #pragma unroll
    for (int s = 0; s < 2; s++) {
        int l = t + s * 256;
        int j = jtile + l;
        float4 b = (j < nval) ? g_cbox[j] : make_float4(0,0,0,0);
        cb[l]  = b;
        car[l] = (b.z - b.x) * (b.w - b.y);
    }
    __syncthreads();

    const int i = i0 + t;
    if (i >= nval) return;
    const float4 B  = g_cbox[i];
    const float  AR = (B.z - B.x) * (B.w - B.y);

    #pragma unroll
    for (int k = 0; k < WG; k++) {
        const int w_idx = by * WG + k;
        const int jbase = w_idx * 64;
        if (jbase + 63 <= i) continue;                   // word entirely j<=i: never read
        const int qlo  = max(0, i + 1 - jbase);          // strict j > i
        const int qmax = min(64, nval - jbase);
        unsigned long long w = 0;
        #pragma unroll 4
        for (int q = qlo; q < qmax; q++) {
            const int l = k * 64 + q;
            float4 b = cb[l];
            float lx = fmaxf(B.x, b.x), ly = fmaxf(B.y, b.y);
            float rx = fminf(B.z, b.z), ry = fminf(B.w, b.w);
            float inter = fmaxf(rx - lx, 0.0f) * fmaxf(ry - ly, 0.0f);
            float denom = ((AR + car[l]) - inter) + 1e-9f;   // reference association order
            bool hit;
            if (inter > denom * (NMS_THR * 1.000001f))      hit = true;
            else if (inter < denom * (NMS_THR * 0.999999f)) hit = false;
            else hit = (inter / denom) > NMS_THR;            // exact (rare boundary)
            if (hit) w |= 1ull << q;
        }
        g_mask[i * NCHUNK + w_idx] = w;
    }
}

// ================= kernel C: serial sweep + output (single block, 256 thr) =================
__global__ void __launch_bounds__(256, 1)
sweep_kernel(const float* __restrict__ box, float* __restrict__ out)
{
    __shared__ unsigned long long rem[NCHUNK];
    __shared__ unsigned long long colbuf[2][64];
    __shared__ int   klist[64];
    __shared__ int   keptidx[MAX_KEEP];
    __shared__ int   s_kc, s_kcn;
    __shared__ int   s_orig[MAX_KEEP];

    const int tid  = threadIdx.x;
    const int nval = g_nval;
    const int nchunk = (nval + 63) >> 6;

    if (tid < NCHUNK) rem[tid] = 0ull;
    if (tid == 0) { s_kc = 0; s_kcn = 0; }
    if (tid < 64 && tid < nval)
        colbuf[0][tid] = g_mask[tid * NCHUNK + 0];
    __syncthreads();

    for (int c = 0; c < nchunk; c++) {
        // prefetch next chunk's diagonal column (threads 192..255) while thread 0 resolves
        if (tid >= 192 && c + 1 < nchunk) {
            int t = tid - 192;
            int i = (c + 1) * 64 + t;
            if (i < nval)
                colbuf[(c + 1) & 1][t] = g_mask[i * NCHUNK + (c + 1)];
        }
        if (tid == 0) {
            int rembits = nval - c * 64;
            unsigned long long validw = (rembits >= 64) ? ~0ull : ((1ull << rembits) - 1ull);
            unsigned long long alive = validw & ~rem[c];
            const unsigned long long* col = colbuf[c & 1];
            int kc = s_kc, n = 0;
            while (alive && kc < MAX_KEEP) {
                int t = __ffsll((long long)alive) - 1;
                keptidx[kc++] = c * 64 + t;
                klist[n++] = t;
                alive &= ~col[t];
                alive &= ~(1ull << t);
            }
            s_kc = kc; s_kcn = n;
        }
        __syncthreads();

        // propagate new kept rows into rem (skip the barrier entirely when none kept)
        const int n = s_kcn;
        if (n) {
            int w = c + 1 + tid;
            if (w < nchunk) {
                const int base = c * 64;
                unsigned long long acc = 0;
                for (int q = 0; q < n; q++)
                    acc |= g_mask[(base + klist[q]) * NCHUNK + w];
                rem[w] |= acc;
            }
            __syncthreads();
            if (s_kc >= MAX_KEEP) break;
        }
    }

    // ---------------- outputs ----------------
    // layout: [0,256) score | [256,4352) box (256x16) | [4352,4608) valid
    const int kc = s_kc;
    for (int k = tid; k < MAX_KEEP; k += 256) {
        if (k < kc) {
            unsigned long long key = g_key[keptidx[k]];
            s_orig[k]     = (int)(key & 0xFFFFFFFFull);
            out[k]        = __uint_as_float(~(unsigned int)(key >> 32));
            out[4352 + k] = 1.0f;
        } else {
            out[k]        = 0.0f;
            out[4352 + k] = 0.0f;
        }
    }
    __syncthreads();
    for (int e = tid; e < MAX_KEEP * 16; e += 256) {
        int k = e >> 4, c = e & 15;
        out[256 + e] = (k < kc) ? box[s_orig[k] * 16 + c] : 0.0f;
    }
}

// ---------------- launch ----------------
extern "C" void kernel_launch(void* const* d_in, const int* in_sizes, int n_in,
                              void* d_out, int out_size) {
    const float* score = (const float*)d_in[0];
    const float* box   = (const float*)d_in[1];
    float* out = (float*)d_out;

    const int dynA = 131072;   // 64K keys + 32K hist + 32K offsets
    cudaFuncSetAttribute(sort_kernel,
                         cudaFuncAttributeMaxDynamicSharedMemorySize, dynA);

    sort_kernel<<<1, NT, dynA>>>(score, box);
    mask_kernel<<<dim3(32, 16), 256>>>();
    sweep_kernel<<<1, 256>>>(box, out);
}